// round 16
// baseline (speedup 1.0000x reference)
#include <cuda_runtime.h>
#include <cuda_fp16.h>
#include <cstdint>

#define NN 100000
#define NE 1600000
#define F  128

// ---------------- scratch (device globals: no allocation allowed) ----------
__device__ __align__(16) __half g_hhalf[(size_t)NN * F];   // 25.6 MB: emb/h1 fp16
__device__ __align__(16) __half g_mean16[(size_t)NN * F];  // 25.6 MB: mean fp16
__device__ __align__(16) __half g_w16[4][F * F];           // W^T fp16: [n][k]
__device__ __align__(16) int g_rowptr[NN + 4];
__device__ __align__(16) int g_fill[NN + 4];
__device__ int g_csr[NE];
__device__ int g_tilesum[64];

// ---------------- fused prep: hist(x4 ILP) || emb->fp16 || weights->fp16^T ---
__global__ void k_prep(const float* __restrict__ emb,
                       const float* __restrict__ w0, const float* __restrict__ w1,
                       const float* __restrict__ w2, const float* __restrict__ w3,
                       const int* __restrict__ dst, int E, int n4,
                       int histBlocks, int cvtBlocks) {
    int b = blockIdx.x;
    int t = threadIdx.x;
    if (b < histBlocks) {
        int i = (b * 256 + t) * 4;
        if (i + 3 < E) {
            int4 d = *(const int4*)(dst + i);
            atomicAdd(&g_rowptr[d.x + 1], 1);
            atomicAdd(&g_rowptr[d.y + 1], 1);
            atomicAdd(&g_rowptr[d.z + 1], 1);
            atomicAdd(&g_rowptr[d.w + 1], 1);
        } else {
            for (; i < E; i++) atomicAdd(&g_rowptr[dst[i] + 1], 1);
        }
    } else if (b < histBlocks + cvtBlocks) {
        int i = (b - histBlocks) * 256 + t;
        if (i < n4) {
            float4 v = *(const float4*)(emb + (size_t)i * 4);
            __half2 h0 = __floats2half2_rn(v.x, v.y);
            __half2 h1 = __floats2half2_rn(v.z, v.w);
            uint2 u;
            u.x = *(uint32_t*)&h0; u.y = *(uint32_t*)&h1;
            *(uint2*)(g_hhalf + (size_t)i * 4) = u;
        }
    } else {
        int i = (b - histBlocks - cvtBlocks) * 256 + t;
        if (i < 4 * F * F) {
            int mat = i >> 14, idx = i & (F * F - 1);
            int k = idx >> 7, n = idx & 127;
            const float* w = mat == 0 ? w0 : mat == 1 ? w1 : mat == 2 ? w2 : w3;
            g_w16[mat][n * F + k] = __float2half_rn(w[idx]);
        }
    }
}

// ---------------- parallel scan (two-kernel, int4-vectorized) ----------------
#define SCAN_TILE 4096
__global__ void __launch_bounds__(1024) k_scan1(int n) {
    __shared__ int ws[32];
    int t = threadIdx.x;
    int lane = t & 31, wid = t >> 5;
    int base = blockIdx.x * SCAN_TILE + t * 4;
    int v[4];
    if (base + 3 < n) {
        int4 t4 = *(const int4*)(g_rowptr + base);
        v[0] = t4.x; v[1] = t4.y; v[2] = t4.z; v[3] = t4.w;
    } else {
#pragma unroll
        for (int j = 0; j < 4; j++) v[j] = (base + j < n) ? g_rowptr[base + j] : 0;
    }
    int s = v[0] + v[1] + v[2] + v[3];
    int sv = s;
#pragma unroll
    for (int o = 1; o < 32; o <<= 1) {
        int tmp = __shfl_up_sync(0xffffffffu, sv, o);
        if (lane >= o) sv += tmp;
    }
    if (lane == 31) ws[wid] = sv;
    __syncthreads();
    if (wid == 0) {
        int w = ws[lane];
#pragma unroll
        for (int o = 1; o < 32; o <<= 1) {
            int tmp = __shfl_up_sync(0xffffffffu, w, o);
            if (lane >= o) w += tmp;
        }
        ws[lane] = w;
    }
    __syncthreads();
    int excl = sv - s + (wid > 0 ? ws[wid - 1] : 0);
    int4 o4;
    o4.x = excl + v[0];
    o4.y = o4.x + v[1];
    o4.z = o4.y + v[2];
    o4.w = o4.z + v[3];
    if (base + 3 < n) {
        *(int4*)(g_rowptr + base) = o4;
    } else {
        int run = excl;
#pragma unroll
        for (int j = 0; j < 4; j++) {
            run += v[j];
            if (base + j < n) g_rowptr[base + j] = run;
        }
    }
    if (t == 1023) g_tilesum[blockIdx.x] = ws[31];
}

__global__ void __launch_bounds__(1024) k_scan3(int n, int nblocks) {
    __shared__ int s_off;
    if (threadIdx.x < 32) {
        int lane = threadIdx.x;
        int v = (lane < nblocks) ? g_tilesum[lane] : 0;
        int sv = v;
#pragma unroll
        for (int o = 1; o < 32; o <<= 1) {
            int t = __shfl_up_sync(0xffffffffu, sv, o);
            if (lane >= o) sv += t;
        }
        if (lane == blockIdx.x) s_off = sv - v;
    }
    __syncthreads();
    int off = s_off;
    int base = blockIdx.x * SCAN_TILE + threadIdx.x * 4;
    if (base + 4 < n) {
        int4 t4 = *(const int4*)(g_rowptr + base);
        t4.x += off; t4.y += off; t4.z += off; t4.w += off;
        *(int4*)(g_rowptr + base) = t4;
        *(int4*)(g_fill + base) = t4;
    } else {
#pragma unroll
        for (int j = 0; j < 4; j++) {
            int i = base + j;
            if (i < n) {
                int val = g_rowptr[i] + off;
                g_rowptr[i] = val;
                if (i < n - 1) g_fill[i] = val;
            }
        }
    }
}

__global__ void k_scatter(const int* __restrict__ src, const int* __restrict__ dst, int E) {
    int i = (blockIdx.x * blockDim.x + threadIdx.x) * 4;
    if (i + 3 < E) {
        int4 sv = *(const int4*)(src + i);
        int4 dv = *(const int4*)(dst + i);
        int p0 = atomicAdd(&g_fill[dv.x], 1);
        int p1 = atomicAdd(&g_fill[dv.y], 1);
        int p2 = atomicAdd(&g_fill[dv.z], 1);
        int p3 = atomicAdd(&g_fill[dv.w], 1);
        g_csr[p0] = sv.x; g_csr[p1] = sv.y;
        g_csr[p2] = sv.z; g_csr[p3] = sv.w;
    } else {
        for (; i < E; i++) {
            int pos = atomicAdd(&g_fill[dst[i]], 1);
            g_csr[pos] = src[i];
        }
    }
}

// ---------------- mean aggregation: warp/node, 2-rows-per-step uint4 ---------
// Lanes 0-15 handle even neighbors, lanes 16-31 odd. Each lane owns 8 features
// (fl*8 .. fl*8+7). Final shfl_xor(16) merges the two neighbor partitions.
__global__ void k_agg(int M) {
    int node = (blockIdx.x * blockDim.x + threadIdx.x) >> 5;
    if (node >= M) return;
    int lane = threadIdx.x & 31;
    int half_id = lane >> 4;       // 0: even neighbors, 1: odd
    int fl = lane & 15;            // feature group: halves fl*8 .. fl*8+7
    int s0 = g_rowptr[node], s1 = g_rowptr[node + 1];
    int deg = s1 - s0;
    float acc[8];
#pragma unroll
    for (int i = 0; i < 8; i++) acc[i] = 0.f;

    int c = s0;
    while (c < s1) {
        int cnt = min(32, s1 - c);
        int idx = 0;
        if (lane < cnt) idx = g_csr[c + lane];
        int j = 0;
        // 8 neighbors per iteration: this lane loads rows j+0/2/4/6 (+half_id)
        for (; j + 8 <= cnt; j += 8) {
            uint4 u[4];
#pragma unroll
            for (int v = 0; v < 4; v++) {
                int a = __shfl_sync(0xffffffffu, idx, j + v * 2 + half_id);
                u[v] = *(const uint4*)(g_hhalf + (size_t)a * F + fl * 8);
            }
#pragma unroll
            for (int p = 0; p < 2; p++) {
                __half2 t0 = __hadd2(*(__half2*)&u[2 * p].x, *(__half2*)&u[2 * p + 1].x);
                __half2 t1 = __hadd2(*(__half2*)&u[2 * p].y, *(__half2*)&u[2 * p + 1].y);
                __half2 t2 = __hadd2(*(__half2*)&u[2 * p].z, *(__half2*)&u[2 * p + 1].z);
                __half2 t3 = __hadd2(*(__half2*)&u[2 * p].w, *(__half2*)&u[2 * p + 1].w);
                float2 f0 = __half22float2(t0), f1 = __half22float2(t1);
                float2 f2 = __half22float2(t2), f3 = __half22float2(t3);
                acc[0] += f0.x; acc[1] += f0.y; acc[2] += f1.x; acc[3] += f1.y;
                acc[4] += f2.x; acc[5] += f2.y; acc[6] += f3.x; acc[7] += f3.y;
            }
        }
        // 2-neighbor tail: lane half takes one row
        for (; j + 2 <= cnt; j += 2) {
            int a = __shfl_sync(0xffffffffu, idx, j + half_id);
            uint4 u = *(const uint4*)(g_hhalf + (size_t)a * F + fl * 8);
            float2 f0 = __half22float2(*(__half2*)&u.x);
            float2 f1 = __half22float2(*(__half2*)&u.y);
            float2 f2 = __half22float2(*(__half2*)&u.z);
            float2 f3 = __half22float2(*(__half2*)&u.w);
            acc[0] += f0.x; acc[1] += f0.y; acc[2] += f1.x; acc[3] += f1.y;
            acc[4] += f2.x; acc[5] += f2.y; acc[6] += f3.x; acc[7] += f3.y;
        }
        // single-neighbor remainder: only even half loads
        if (j < cnt) {
            int a = __shfl_sync(0xffffffffu, idx, j);
            if (half_id == 0) {
                uint4 u = *(const uint4*)(g_hhalf + (size_t)a * F + fl * 8);
                float2 f0 = __half22float2(*(__half2*)&u.x);
                float2 f1 = __half22float2(*(__half2*)&u.y);
                float2 f2 = __half22float2(*(__half2*)&u.z);
                float2 f3 = __half22float2(*(__half2*)&u.w);
                acc[0] += f0.x; acc[1] += f0.y; acc[2] += f1.x; acc[3] += f1.y;
                acc[4] += f2.x; acc[5] += f2.y; acc[6] += f3.x; acc[7] += f3.y;
            }
        }
        c += cnt;
    }

    // merge even/odd neighbor partitions (feature-aligned across half groups)
#pragma unroll
    for (int i = 0; i < 8; i++)
        acc[i] += __shfl_xor_sync(0xffffffffu, acc[i], 16);

    float inv = 1.0f / (float)max(deg, 1);
    if (half_id == 0) {
        __half2 h0 = __floats2half2_rn(acc[0] * inv, acc[1] * inv);
        __half2 h1 = __floats2half2_rn(acc[2] * inv, acc[3] * inv);
        __half2 h2 = __floats2half2_rn(acc[4] * inv, acc[5] * inv);
        __half2 h3 = __floats2half2_rn(acc[6] * inv, acc[7] * inv);
        uint4 o;
        o.x = *(uint32_t*)&h0; o.y = *(uint32_t*)&h1;
        o.z = *(uint32_t*)&h2; o.w = *(uint32_t*)&h3;
        *(uint4*)(g_mean16 + (size_t)node * F + fl * 8) = o;
    }
}

// ---------------- mma / cp.async / ldmatrix helpers ---------------------------
__device__ __forceinline__ void mma_f16(float* c, const uint32_t* a, const uint32_t* b) {
    asm volatile(
        "mma.sync.aligned.m16n8k16.row.col.f32.f16.f16.f32 "
        "{%0,%1,%2,%3}, {%4,%5,%6,%7}, {%8,%9}, {%0,%1,%2,%3};"
        : "+f"(c[0]), "+f"(c[1]), "+f"(c[2]), "+f"(c[3])
        : "r"(a[0]), "r"(a[1]), "r"(a[2]), "r"(a[3]), "r"(b[0]), "r"(b[1]));
}

__device__ __forceinline__ void ldsm4(uint32_t& r0, uint32_t& r1, uint32_t& r2,
                                      uint32_t& r3, uint32_t addr) {
    asm volatile("ldmatrix.sync.aligned.m8n8.x4.shared.b16 {%0,%1,%2,%3}, [%4];"
                 : "=r"(r0), "=r"(r1), "=r"(r2), "=r"(r3) : "r"(addr));
}

__device__ __forceinline__ void cp16(uint32_t dst, const void* src, int sz) {
    asm volatile("cp.async.cg.shared.global [%0], [%1], 16, %2;\n"
                 :: "r"(dst), "l"(src), "r"(sz));
}
__device__ __forceinline__ void cp_commit() {
    asm volatile("cp.async.commit_group;\n" ::: "memory");
}
template <int N>
__device__ __forceinline__ void cp_wait() {
    asm volatile("cp.async.wait_group %0;\n" :: "n"(N) : "memory");
}

// ---------------- fused dual-GEMM fp16, BM=128 (proven round-12 config) ------
#define STW 20                // words per smem row (stride 80B)
#define STAGE_W (128 * STW)   // words per stage per matrix
template <bool LAYER1>
__global__ void __launch_bounds__(256, 2)
k_gemm_mma(const float* __restrict__ bias, float* __restrict__ out, int M) {
    const __half* __restrict__ ws = g_w16[LAYER1 ? 0 : 2];
    const __half* __restrict__ wn = g_w16[LAYER1 ? 1 : 3];

    extern __shared__ uint32_t smem[];
    uint32_t smem_u32 = (uint32_t)__cvta_generic_to_shared(smem);

    int tid = threadIdx.x;
    int wid = tid >> 5, lane = tid & 31;
    int warp_m = (wid & 1) * 64;
    int warp_n = (wid >> 1) * 32;
    int base = blockIdx.x * 128;
    int qr = lane >> 2, qc = lane & 3;

    int r0 = tid >> 1;
    int s0h = (tid & 1) * 16;

    int a_row_add = ((lane >> 3) & 1) * 8 + (lane & 7);
    int a_col_w   = ((lane >> 4) & 1) * 4;
    uint32_t a_off[4];
#pragma unroll
    for (int mt = 0; mt < 4; mt++)
        a_off[mt] = ((warp_m + mt * 16 + a_row_add) * STW + a_col_w) * 4;
    int b_row_add = ((lane >> 4) & 1) * 8 + (lane & 7);
    int b_col_w   = ((lane >> 3) & 1) * 4;
    uint32_t b_off[2];
#pragma unroll
    for (int j = 0; j < 2; j++)
        b_off[j] = ((warp_n + j * 16 + b_row_add) * STW + b_col_w) * 4;

    float acc[4][4][4];
#pragma unroll
    for (int a = 0; a < 4; a++)
#pragma unroll
        for (int b = 0; b < 4; b++)
#pragma unroll
            for (int c = 0; c < 4; c++) acc[a][b][c] = 0.f;

#define LOAD_CHUNK(c, stage)                                                      \
    {                                                                             \
        int p_ = (c) >> 2, kc_ = ((c) & 3) * 32;                                  \
        const __half* A_ = p_ ? g_mean16 : g_hhalf;                               \
        const __half* W_ = p_ ? wn : ws;                                          \
        uint32_t ab = smem_u32 + (uint32_t)(stage) * STAGE_W * 4;                 \
        uint32_t bb = smem_u32 + (3u + (uint32_t)(stage)) * STAGE_W * 4;          \
        int ok = (base + r0 < M) ? 16 : 0;                                        \
        cp16(ab + (r0 * STW) * 4 + s0h * 2,                                       \
             A_ + (size_t)(base + r0) * F + kc_ + s0h, ok);                       \
        cp16(ab + (r0 * STW) * 4 + (s0h + 8) * 2,                                 \
             A_ + (size_t)(base + r0) * F + kc_ + s0h + 8, ok);                   \
        cp16(bb + (r0 * STW) * 4 + s0h * 2,                                       \
             W_ + (size_t)r0 * F + kc_ + s0h, 16);                                \
        cp16(bb + (r0 * STW) * 4 + (s0h + 8) * 2,                                 \
             W_ + (size_t)r0 * F + kc_ + s0h + 8, 16);                            \
    }

    LOAD_CHUNK(0, 0); cp_commit();
    LOAD_CHUNK(1, 1); cp_commit();

    for (int c = 0; c < 8; ++c) {
        if (c == 7) cp_wait<0>();   // last chunk: FULL drain
        else        cp_wait<1>();
        __syncthreads();
        if (c + 2 < 8) {
            LOAD_CHUNK(c + 2, (c + 2) % 3);
            cp_commit();
        }
        int stg = c % 3;
        uint32_t ab = smem_u32 + (uint32_t)stg * STAGE_W * 4;
        uint32_t bb = smem_u32 + (3u + (uint32_t)stg) * STAGE_W * 4;
#pragma unroll
        for (int s = 0; s < 2; s++) {
            uint32_t kb = s * 32;
            uint32_t bfr[4][2];
            ldsm4(bfr[0][0], bfr[0][1], bfr[1][0], bfr[1][1], bb + b_off[0] + kb);
            ldsm4(bfr[2][0], bfr[2][1], bfr[3][0], bfr[3][1], bb + b_off[1] + kb);
#pragma unroll
            for (int mt = 0; mt < 4; mt++) {
                uint32_t afr[4];
                ldsm4(afr[0], afr[1], afr[2], afr[3], ab + a_off[mt] + kb);
#pragma unroll
                for (int nt = 0; nt < 4; nt++)
                    mma_f16(acc[mt][nt], afr, bfr[nt]);
            }
        }
    }

#pragma unroll
    for (int nt = 0; nt < 4; nt++) {
        int col = warp_n + nt * 8 + 2 * qc;
        float b0 = bias[col], b1 = bias[col + 1];
#pragma unroll
        for (int mt = 0; mt < 4; mt++) {
#pragma unroll
            for (int h = 0; h < 2; h++) {
                int row = base + warp_m + mt * 16 + qr + h * 8;
                if (row < M) {
                    float v0 = acc[mt][nt][2 * h] + b0;
                    float v1 = acc[mt][nt][2 * h + 1] + b1;
                    if (LAYER1) {
                        v0 = v0 > 0.f ? v0 : 0.2f * v0;
                        v1 = v1 > 0.f ? v1 : 0.2f * v1;
                        __half2 hv = __floats2half2_rn(v0, v1);
                        *(__half2*)(g_hhalf + (size_t)row * F + col) = hv;
                    } else {
                        float2 vv = make_float2(v0, v1);
                        *(float2*)(out + (size_t)row * F + col) = vv;
                    }
                }
            }
        }
    }
#undef LOAD_CHUNK
}

// ---------------- launch ----------------------------------------------------
extern "C" void kernel_launch(void* const* d_in, const int* in_sizes, int n_in,
                              void* d_out, int out_size) {
    const float* emb = (const float*)d_in[0];
    const float* W1s = (const float*)d_in[1];
    const float* W1n = (const float*)d_in[2];
    const float* b1  = (const float*)d_in[3];
    const float* W2s = (const float*)d_in[4];
    const float* W2n = (const float*)d_in[5];
    const float* b2  = (const float*)d_in[6];
    const int*   edg = (const int*)d_in[7];

    int E = in_sizes[7] / 2;
    int M = in_sizes[0] / F;
    const int* src = edg;
    const int* dst = edg + E;
    float* out = (float*)d_out;

    int n = M + 1;
    int scanBlocks = (n + SCAN_TILE - 1) / SCAN_TILE;
    int n4 = M * F / 4;
    int histBlocks = (E / 4 + 255) / 256;
    int cvtBlocks = (n4 + 255) / 256;
    int wBlocks = (4 * F * F + 255) / 256;
    int scatBlocks = (E / 4 + 255) / 256;

    const int GEMM_SMEM = 6 * STAGE_W * 4;   // 61440 B
    cudaFuncSetAttribute(k_gemm_mma<true>,
                         cudaFuncAttributeMaxDynamicSharedMemorySize, GEMM_SMEM);
    cudaFuncSetAttribute(k_gemm_mma<false>,
                         cudaFuncAttributeMaxDynamicSharedMemorySize, GEMM_SMEM);

    void* rowptr_ptr = nullptr;
    cudaGetSymbolAddress(&rowptr_ptr, g_rowptr);
    cudaMemsetAsync(rowptr_ptr, 0, (size_t)n * sizeof(int), 0);

    k_prep<<<histBlocks + cvtBlocks + wBlocks, 256>>>(
        emb, W1s, W1n, W2s, W2n, dst, E, n4, histBlocks, cvtBlocks);
    k_scan1<<<scanBlocks, 1024>>>(n);
    k_scan3<<<scanBlocks, 1024>>>(n, scanBlocks);
    k_scatter<<<scatBlocks, 256>>>(src, dst, E);

    int aggBlocks = (M * 32 + 255) / 256;
    int gemmBlocks = (M + 127) / 128;

    // layer 1
    k_agg<<<aggBlocks, 256>>>(M);
    k_gemm_mma<true><<<gemmBlocks, 256, GEMM_SMEM>>>(b1, nullptr, M);

    // layer 2
    k_agg<<<aggBlocks, 256>>>(M);
    k_gemm_mma<false><<<gemmBlocks, 256, GEMM_SMEM>>>(b2, out, M);
}

// round 17
// speedup vs baseline: 1.0509x; 1.0509x over previous
#include <cuda_runtime.h>
#include <cuda_fp16.h>
#include <cstdint>

#define NN 100000
#define NE 1600000
#define F  128

// ---------------- scratch (device globals: no allocation allowed) ----------
__device__ __align__(16) __half g_hhalf[(size_t)NN * F];   // 25.6 MB: emb/h1 fp16
__device__ __align__(16) __half g_mean16[(size_t)NN * F];  // 25.6 MB: mean fp16
__device__ __align__(16) __half g_w16[4][F * F];           // W^T fp16: [n][k]
__device__ __align__(16) int g_rowptr[NN + 4];
__device__ __align__(16) int g_fill[NN + 4];
__device__ int g_csr[NE];
__device__ int g_tilesum[64];

// ---------------- fused prep: hist(x4 ILP) || emb->fp16 || weights->fp16^T ---
__global__ void k_prep(const float* __restrict__ emb,
                       const float* __restrict__ w0, const float* __restrict__ w1,
                       const float* __restrict__ w2, const float* __restrict__ w3,
                       const int* __restrict__ dst, int E, int n4,
                       int histBlocks, int cvtBlocks) {
    int b = blockIdx.x;
    int t = threadIdx.x;
    if (b < histBlocks) {
        int i = (b * 256 + t) * 4;
        if (i + 3 < E) {
            int4 d = *(const int4*)(dst + i);
            atomicAdd(&g_rowptr[d.x + 1], 1);
            atomicAdd(&g_rowptr[d.y + 1], 1);
            atomicAdd(&g_rowptr[d.z + 1], 1);
            atomicAdd(&g_rowptr[d.w + 1], 1);
        } else {
            for (; i < E; i++) atomicAdd(&g_rowptr[dst[i] + 1], 1);
        }
    } else if (b < histBlocks + cvtBlocks) {
        int i = (b - histBlocks) * 256 + t;
        if (i < n4) {
            float4 v = *(const float4*)(emb + (size_t)i * 4);
            __half2 h0 = __floats2half2_rn(v.x, v.y);
            __half2 h1 = __floats2half2_rn(v.z, v.w);
            uint2 u;
            u.x = *(uint32_t*)&h0; u.y = *(uint32_t*)&h1;
            *(uint2*)(g_hhalf + (size_t)i * 4) = u;
        }
    } else {
        int i = (b - histBlocks - cvtBlocks) * 256 + t;
        if (i < 4 * F * F) {
            int mat = i >> 14, idx = i & (F * F - 1);
            int k = idx >> 7, n = idx & 127;
            const float* w = mat == 0 ? w0 : mat == 1 ? w1 : mat == 2 ? w2 : w3;
            g_w16[mat][n * F + k] = __float2half_rn(w[idx]);
        }
    }
}

// ---------------- parallel scan (two-kernel, int4-vectorized) ----------------
#define SCAN_TILE 4096
__global__ void __launch_bounds__(1024) k_scan1(int n) {
    __shared__ int ws[32];
    int t = threadIdx.x;
    int lane = t & 31, wid = t >> 5;
    int base = blockIdx.x * SCAN_TILE + t * 4;
    int v[4];
    if (base + 3 < n) {
        int4 t4 = *(const int4*)(g_rowptr + base);
        v[0] = t4.x; v[1] = t4.y; v[2] = t4.z; v[3] = t4.w;
    } else {
#pragma unroll
        for (int j = 0; j < 4; j++) v[j] = (base + j < n) ? g_rowptr[base + j] : 0;
    }
    int s = v[0] + v[1] + v[2] + v[3];
    int sv = s;
#pragma unroll
    for (int o = 1; o < 32; o <<= 1) {
        int tmp = __shfl_up_sync(0xffffffffu, sv, o);
        if (lane >= o) sv += tmp;
    }
    if (lane == 31) ws[wid] = sv;
    __syncthreads();
    if (wid == 0) {
        int w = ws[lane];
#pragma unroll
        for (int o = 1; o < 32; o <<= 1) {
            int tmp = __shfl_up_sync(0xffffffffu, w, o);
            if (lane >= o) w += tmp;
        }
        ws[lane] = w;
    }
    __syncthreads();
    int excl = sv - s + (wid > 0 ? ws[wid - 1] : 0);
    int4 o4;
    o4.x = excl + v[0];
    o4.y = o4.x + v[1];
    o4.z = o4.y + v[2];
    o4.w = o4.z + v[3];
    if (base + 3 < n) {
        *(int4*)(g_rowptr + base) = o4;
    } else {
        int run = excl;
#pragma unroll
        for (int j = 0; j < 4; j++) {
            run += v[j];
            if (base + j < n) g_rowptr[base + j] = run;
        }
    }
    if (t == 1023) g_tilesum[blockIdx.x] = ws[31];
}

__global__ void __launch_bounds__(1024) k_scan3(int n, int nblocks) {
    __shared__ int s_off;
    if (threadIdx.x < 32) {
        int lane = threadIdx.x;
        int v = (lane < nblocks) ? g_tilesum[lane] : 0;
        int sv = v;
#pragma unroll
        for (int o = 1; o < 32; o <<= 1) {
            int t = __shfl_up_sync(0xffffffffu, sv, o);
            if (lane >= o) sv += t;
        }
        if (lane == blockIdx.x) s_off = sv - v;
    }
    __syncthreads();
    int off = s_off;
    int base = blockIdx.x * SCAN_TILE + threadIdx.x * 4;
    if (base + 4 < n) {
        int4 t4 = *(const int4*)(g_rowptr + base);
        t4.x += off; t4.y += off; t4.z += off; t4.w += off;
        *(int4*)(g_rowptr + base) = t4;
        *(int4*)(g_fill + base) = t4;
    } else {
#pragma unroll
        for (int j = 0; j < 4; j++) {
            int i = base + j;
            if (i < n) {
                int val = g_rowptr[i] + off;
                g_rowptr[i] = val;
                if (i < n - 1) g_fill[i] = val;
            }
        }
    }
}

__global__ void k_scatter(const int* __restrict__ src, const int* __restrict__ dst, int E) {
    int i = (blockIdx.x * blockDim.x + threadIdx.x) * 4;
    if (i + 3 < E) {
        int4 sv = *(const int4*)(src + i);
        int4 dv = *(const int4*)(dst + i);
        int p0 = atomicAdd(&g_fill[dv.x], 1);
        int p1 = atomicAdd(&g_fill[dv.y], 1);
        int p2 = atomicAdd(&g_fill[dv.z], 1);
        int p3 = atomicAdd(&g_fill[dv.w], 1);
        g_csr[p0] = sv.x; g_csr[p1] = sv.y;
        g_csr[p2] = sv.z; g_csr[p3] = sv.w;
    } else {
        for (; i < E; i++) {
            int pos = atomicAdd(&g_fill[dst[i]], 1);
            g_csr[pos] = src[i];
        }
    }
}

// ---------------- mean aggregation: warp/node, depth-1 hadd2 (round-12) ------
__global__ void k_agg(int M) {
    int node = (blockIdx.x * blockDim.x + threadIdx.x) >> 5;
    if (node >= M) return;
    int lane = threadIdx.x & 31;
    int s0 = g_rowptr[node], s1 = g_rowptr[node + 1];
    int deg = s1 - s0;
    float4 acc = make_float4(0.f, 0.f, 0.f, 0.f);
    int c = s0;
    while (c < s1) {
        int cnt = min(32, s1 - c);
        int idx = 0;
        if (lane < cnt) idx = g_csr[c + lane];
        int j = 0;
        for (; j + 8 <= cnt; j += 8) {
            uint2 u[8];
#pragma unroll
            for (int v = 0; v < 8; v++) {
                int a = __shfl_sync(0xffffffffu, idx, j + v);
                u[v] = *(const uint2*)(g_hhalf + (size_t)a * F + lane * 4);
            }
#pragma unroll
            for (int p = 0; p < 4; p++) {
                __half2 t0 = __hadd2(*(__half2*)&u[2 * p].x, *(__half2*)&u[2 * p + 1].x);
                __half2 t1 = __hadd2(*(__half2*)&u[2 * p].y, *(__half2*)&u[2 * p + 1].y);
                float2 f0 = __half22float2(t0), f1 = __half22float2(t1);
                acc.x += f0.x; acc.y += f0.y; acc.z += f1.x; acc.w += f1.y;
            }
        }
        for (; j + 2 <= cnt; j += 2) {
            int a = __shfl_sync(0xffffffffu, idx, j);
            int b = __shfl_sync(0xffffffffu, idx, j + 1);
            uint2 ua = *(const uint2*)(g_hhalf + (size_t)a * F + lane * 4);
            uint2 ub = *(const uint2*)(g_hhalf + (size_t)b * F + lane * 4);
            __half2 t0 = __hadd2(*(__half2*)&ua.x, *(__half2*)&ub.x);
            __half2 t1 = __hadd2(*(__half2*)&ua.y, *(__half2*)&ub.y);
            float2 f0 = __half22float2(t0), f1 = __half22float2(t1);
            acc.x += f0.x; acc.y += f0.y; acc.z += f1.x; acc.w += f1.y;
        }
        if (j < cnt) {
            int a = __shfl_sync(0xffffffffu, idx, j);
            uint2 u = *(const uint2*)(g_hhalf + (size_t)a * F + lane * 4);
            float2 f0 = __half22float2(*(__half2*)&u.x);
            float2 f1 = __half22float2(*(__half2*)&u.y);
            acc.x += f0.x; acc.y += f0.y; acc.z += f1.x; acc.w += f1.y;
        }
        c += cnt;
    }
    float inv = 1.0f / (float)max(deg, 1);
    __half2 m0 = __floats2half2_rn(acc.x * inv, acc.y * inv);
    __half2 m1 = __floats2half2_rn(acc.z * inv, acc.w * inv);
    uint2 u;
    u.x = *(uint32_t*)&m0; u.y = *(uint32_t*)&m1;
    *(uint2*)(g_mean16 + (size_t)node * F + lane * 4) = u;
}

// ---------------- mma / cp.async / ldmatrix helpers ---------------------------
__device__ __forceinline__ void mma_f16(float* c, const uint32_t* a, const uint32_t* b) {
    asm volatile(
        "mma.sync.aligned.m16n8k16.row.col.f32.f16.f16.f32 "
        "{%0,%1,%2,%3}, {%4,%5,%6,%7}, {%8,%9}, {%0,%1,%2,%3};"
        : "+f"(c[0]), "+f"(c[1]), "+f"(c[2]), "+f"(c[3])
        : "r"(a[0]), "r"(a[1]), "r"(a[2]), "r"(a[3]), "r"(b[0]), "r"(b[1]));
}

__device__ __forceinline__ void ldsm4(uint32_t& r0, uint32_t& r1, uint32_t& r2,
                                      uint32_t& r3, uint32_t addr) {
    asm volatile("ldmatrix.sync.aligned.m8n8.x4.shared.b16 {%0,%1,%2,%3}, [%4];"
                 : "=r"(r0), "=r"(r1), "=r"(r2), "=r"(r3) : "r"(addr));
}

__device__ __forceinline__ void cp16(uint32_t dst, const void* src, int sz) {
    asm volatile("cp.async.cg.shared.global [%0], [%1], 16, %2;\n"
                 :: "r"(dst), "l"(src), "r"(sz));
}
__device__ __forceinline__ void cp_commit() {
    asm volatile("cp.async.commit_group;\n" ::: "memory");
}
template <int N>
__device__ __forceinline__ void cp_wait() {
    asm volatile("cp.async.wait_group %0;\n" :: "n"(N) : "memory");
}

// ---------------- fused dual-GEMM fp16, BM=128, PERSISTENT CTAs --------------
#define STW 20                // words per smem row (stride 80B)
#define STAGE_W (128 * STW)   // words per stage per matrix
template <bool LAYER1>
__global__ void __launch_bounds__(256, 2)
k_gemm_mma(const float* __restrict__ bias, float* __restrict__ out, int M, int tiles) {
    const __half* __restrict__ ws = g_w16[LAYER1 ? 0 : 2];
    const __half* __restrict__ wn = g_w16[LAYER1 ? 1 : 3];

    extern __shared__ uint32_t smem[];
    uint32_t smem_u32 = (uint32_t)__cvta_generic_to_shared(smem);

    int tid = threadIdx.x;
    int wid = tid >> 5, lane = tid & 31;
    int warp_m = (wid & 1) * 64;
    int warp_n = (wid >> 1) * 32;
    int qr = lane >> 2, qc = lane & 3;

    int r0 = tid >> 1;
    int s0h = (tid & 1) * 16;

    int a_row_add = ((lane >> 3) & 1) * 8 + (lane & 7);
    int a_col_w   = ((lane >> 4) & 1) * 4;
    uint32_t a_off[4];
#pragma unroll
    for (int mt = 0; mt < 4; mt++)
        a_off[mt] = ((warp_m + mt * 16 + a_row_add) * STW + a_col_w) * 4;
    int b_row_add = ((lane >> 4) & 1) * 8 + (lane & 7);
    int b_col_w   = ((lane >> 3) & 1) * 4;
    uint32_t b_off[2];
#pragma unroll
    for (int j = 0; j < 2; j++)
        b_off[j] = ((warp_n + j * 16 + b_row_add) * STW + b_col_w) * 4;

    // bias hoisted: constant across tiles
    float bia[4][2];
#pragma unroll
    for (int nt = 0; nt < 4; nt++) {
        int col = warp_n + nt * 8 + 2 * qc;
        bia[nt][0] = bias[col];
        bia[nt][1] = bias[col + 1];
    }

#define LOAD_CHUNK(c, stage)                                                      \
    {                                                                             \
        int p_ = (c) >> 2, kc_ = ((c) & 3) * 32;                                  \
        const __half* A_ = p_ ? g_mean16 : g_hhalf;                               \
        const __half* W_ = p_ ? wn : ws;                                          \
        uint32_t ab = smem_u32 + (uint32_t)(stage) * STAGE_W * 4;                 \
        uint32_t bb = smem_u32 + (3u + (uint32_t)(stage)) * STAGE_W * 4;          \
        int ok = (base + r0 < M) ? 16 : 0;                                        \
        cp16(ab + (r0 * STW) * 4 + s0h * 2,                                       \
             A_ + (size_t)(base + r0) * F + kc_ + s0h, ok);                       \
        cp16(ab + (r0 * STW) * 4 + (s0h + 8) * 2,                                 \
             A_ + (size_t)(base + r0) * F + kc_ + s0h + 8, ok);                   \
        cp16(bb + (r0 * STW) * 4 + s0h * 2,                                       \
             W_ + (size_t)r0 * F + kc_ + s0h, 16);                                \
        cp16(bb + (r0 * STW) * 4 + (s0h + 8) * 2,                                 \
             W_ + (size_t)r0 * F + kc_ + s0h + 8, 16);                            \
    }

    for (int tile = blockIdx.x; tile < tiles; tile += gridDim.x) {
        int base = tile * 128;
        __syncthreads();   // all smem reads of previous tile complete

        float acc[4][4][4];
#pragma unroll
        for (int a = 0; a < 4; a++)
#pragma unroll
            for (int b = 0; b < 4; b++)
#pragma unroll
                for (int c = 0; c < 4; c++) acc[a][b][c] = 0.f;

        LOAD_CHUNK(0, 0); cp_commit();
        LOAD_CHUNK(1, 1); cp_commit();

        for (int c = 0; c < 8; ++c) {
            if (c == 7) cp_wait<0>();   // last chunk: FULL drain (race fix)
            else        cp_wait<1>();
            __syncthreads();
            if (c + 2 < 8) {
                LOAD_CHUNK(c + 2, (c + 2) % 3);
                cp_commit();
            }
            int stg = c % 3;
            uint32_t ab = smem_u32 + (uint32_t)stg * STAGE_W * 4;
            uint32_t bb = smem_u32 + (3u + (uint32_t)stg) * STAGE_W * 4;
#pragma unroll
            for (int s = 0; s < 2; s++) {
                uint32_t kb = s * 32;
                uint32_t bfr[4][2];
                ldsm4(bfr[0][0], bfr[0][1], bfr[1][0], bfr[1][1], bb + b_off[0] + kb);
                ldsm4(bfr[2][0], bfr[2][1], bfr[3][0], bfr[3][1], bb + b_off[1] + kb);
#pragma unroll
                for (int mt = 0; mt < 4; mt++) {
                    uint32_t afr[4];
                    ldsm4(afr[0], afr[1], afr[2], afr[3], ab + a_off[mt] + kb);
#pragma unroll
                    for (int nt = 0; nt < 4; nt++)
                        mma_f16(acc[mt][nt], afr, bfr[nt]);
                }
            }
        }

        // epilogue
#pragma unroll
        for (int nt = 0; nt < 4; nt++) {
            int col = warp_n + nt * 8 + 2 * qc;
#pragma unroll
            for (int mt = 0; mt < 4; mt++) {
#pragma unroll
                for (int h = 0; h < 2; h++) {
                    int row = base + warp_m + mt * 16 + qr + h * 8;
                    if (row < M) {
                        float v0 = acc[mt][nt][2 * h] + bia[nt][0];
                        float v1 = acc[mt][nt][2 * h + 1] + bia[nt][1];
                        if (LAYER1) {
                            v0 = v0 > 0.f ? v0 : 0.2f * v0;
                            v1 = v1 > 0.f ? v1 : 0.2f * v1;
                            __half2 hv = __floats2half2_rn(v0, v1);
                            *(__half2*)(g_hhalf + (size_t)row * F + col) = hv;
                        } else {
                            float2 vv = make_float2(v0, v1);
                            *(float2*)(out + (size_t)row * F + col) = vv;
                        }
                    }
                }
            }
        }
    }
#undef LOAD_CHUNK
}

// ---------------- launch ----------------------------------------------------
extern "C" void kernel_launch(void* const* d_in, const int* in_sizes, int n_in,
                              void* d_out, int out_size) {
    const float* emb = (const float*)d_in[0];
    const float* W1s = (const float*)d_in[1];
    const float* W1n = (const float*)d_in[2];
    const float* b1  = (const float*)d_in[3];
    const float* W2s = (const float*)d_in[4];
    const float* W2n = (const float*)d_in[5];
    const float* b2  = (const float*)d_in[6];
    const int*   edg = (const int*)d_in[7];

    int E = in_sizes[7] / 2;
    int M = in_sizes[0] / F;
    const int* src = edg;
    const int* dst = edg + E;
    float* out = (float*)d_out;

    int n = M + 1;
    int scanBlocks = (n + SCAN_TILE - 1) / SCAN_TILE;
    int n4 = M * F / 4;
    int histBlocks = (E / 4 + 255) / 256;
    int cvtBlocks = (n4 + 255) / 256;
    int wBlocks = (4 * F * F + 255) / 256;
    int scatBlocks = (E / 4 + 255) / 256;

    const int GEMM_SMEM = 6 * STAGE_W * 4;   // 61440 B
    cudaFuncSetAttribute(k_gemm_mma<true>,
                         cudaFuncAttributeMaxDynamicSharedMemorySize, GEMM_SMEM);
    cudaFuncSetAttribute(k_gemm_mma<false>,
                         cudaFuncAttributeMaxDynamicSharedMemorySize, GEMM_SMEM);

    void* rowptr_ptr = nullptr;
    cudaGetSymbolAddress(&rowptr_ptr, g_rowptr);
    cudaMemsetAsync(rowptr_ptr, 0, (size_t)n * sizeof(int), 0);

    k_prep<<<histBlocks + cvtBlocks + wBlocks, 256>>>(
        emb, W1s, W1n, W2s, W2n, dst, E, n4, histBlocks, cvtBlocks);
    k_scan1<<<scanBlocks, 1024>>>(n);
    k_scan3<<<scanBlocks, 1024>>>(n, scanBlocks);
    k_scatter<<<scatBlocks, 256>>>(src, dst, E);

    int aggBlocks = (M * 32 + 255) / 256;
    int tiles = (M + 127) / 128;
    int gemmGrid = tiles < 296 ? tiles : 296;   // persistent: 2 CTAs x 148 SMs

    // layer 1
    k_agg<<<aggBlocks, 256>>>(M);
    k_gemm_mma<true><<<gemmGrid, 256, GEMM_SMEM>>>(b1, nullptr, M, tiles);

    // layer 2
    k_agg<<<aggBlocks, 256>>>(M);
    k_gemm_mma<false><<<gemmGrid, 256, GEMM_SMEM>>>(b2, out, M, tiles);
}